// round 6
// baseline (speedup 1.0000x reference)
#include <cuda_runtime.h>

#define B_ 4
#define N_ 4096
#define D_ 256

// 16 MB scratch for projected_val = val @ Wv  (device-global: no allocation)
static __device__ float g_projval[B_ * N_ * D_];

// ---------- packed f32x2 helpers (Blackwell FFMA2) ----------
__device__ __forceinline__ unsigned long long ffma2(unsigned long long a,
                                                    unsigned long long b,
                                                    unsigned long long c) {
    unsigned long long d;
    asm("fma.rn.f32x2 %0, %1, %2, %3;" : "=l"(d) : "l"(a), "l"(b), "l"(c));
    return d;
}
__device__ __forceinline__ unsigned long long dup2(float x) {
    unsigned long long d;
    asm("mov.b64 %0, {%1, %1};" : "=l"(d) : "f"(x));
    return d;
}
__device__ __forceinline__ float2 unpk(unsigned long long v) {
    float2 r;
    asm("mov.b64 {%0, %1}, %2;" : "=f"(r.x), "=f"(r.y) : "l"(v));
    return r;
}
union V4 {
    float4 f;
    unsigned long long u[2];
};

// =====================================================================
// Kernel 1: g_projval[row][e] = sum_d val[row][d] * Wv[d][e]
// rows = B*N = 16384 flattened. Tile 64 rows x 64 e, k-tile 32.
// 256 threads as (tx 16, ty 16), 4x4 microtile, f32x2 packed FMA.
// =====================================================================
__global__ __launch_bounds__(256, 2)
void proj_kernel(const float* __restrict__ val, const float* __restrict__ Wv) {
    __shared__ float As[64 * 36];   // [row][kk], stride 36 (16B-aligned rows)
    __shared__ float Bs[32 * 68];   // [kk][e],  stride 68 (conflict-free LDS.128)
    const int t = threadIdx.x;
    const int tx = t & 15, ty = t >> 4;
    const int row0 = blockIdx.y * 64;
    const int e0 = blockIdx.x * 64;

    unsigned long long acc[4][2] = {};
    for (int k0 = 0; k0 < D_; k0 += 32) {
#pragma unroll
        for (int p = 0; p < 2; p++) {           // A: 64x32 = 512 float4, 2/thread
            int idx = p * 256 + t;
            int r = idx >> 3, q = idx & 7;
            *(float4*)&As[r * 36 + q * 4] =
                *(const float4*)&val[(size_t)(row0 + r) * D_ + k0 + q * 4];
        }
#pragma unroll
        for (int p = 0; p < 2; p++) {           // B(Wv): 32x64, already k-major
            int idx = p * 256 + t;
            int kr = idx >> 4, ec = idx & 15;
            *(float4*)&Bs[kr * 68 + ec * 4] =
                *(const float4*)&Wv[(k0 + kr) * D_ + e0 + ec * 4];
        }
        __syncthreads();
#pragma unroll 16
        for (int kk = 0; kk < 32; kk++) {
            V4 bv; bv.f = *(float4*)&Bs[kk * 68 + tx * 4];
#pragma unroll
            for (int i = 0; i < 4; i++) {
                unsigned long long a2 = dup2(As[(ty * 4 + i) * 36 + kk]);
                acc[i][0] = ffma2(a2, bv.u[0], acc[i][0]);
                acc[i][1] = ffma2(a2, bv.u[1], acc[i][1]);
            }
        }
        __syncthreads();
    }
#pragma unroll
    for (int i = 0; i < 4; i++) {
        V4 o; o.u[0] = acc[i][0]; o.u[1] = acc[i][1];
        *(float4*)&g_projval[(size_t)(row0 + ty * 4 + i) * D_ + e0 + tx * 4] = o.f;
    }
}

// =====================================================================
// Kernel 2: fused propagation.
// Block = (b, 32 n-rows). Stream m in chunks of 64:
//   Phase A: S[32x64] = Vn @ Vm^T  (fp32, f32x2)
//   softsign -> Es (SMEM), dstate row-reduce with state chunk
//   Phase B: dval[32x256] += Es @ projval_m  (fp32, f32x2)
// 128 threads as (tx 16, ty 8): Phase A 4x4 tile, Phase B 4x(4x float4).
// =====================================================================
__global__ __launch_bounds__(128, 4)
void prop_kernel(const float* __restrict__ val, const float* __restrict__ state,
                 float* __restrict__ out) {
    __shared__ float As[32 * 36];   // Vn rows [row][kk]
    __shared__ float Bs[32 * 68];   // Vm transposed [kk][m-row 64]
    __shared__ float Es[32 * 68];   // edges [n-row 32][m 64]
    __shared__ float Ps[16 * 256];  // projval chunk [m 16][e 256]
    __shared__ float Ss[64];        // state chunk

    const int t = threadIdx.x;
    const int tx = t & 15, ty = t >> 4;   // ty 0..7
    const int b = blockIdx.y;
    const int n0 = blockIdx.x * 32;
    const float* valb = val + (size_t)b * N_ * D_;
    const float* pvb = g_projval + (size_t)b * N_ * D_;

    unsigned long long dval[4][4][2] = {};
    float ds = 0.f;

    for (int m0 = 0; m0 < N_; m0 += 64) {
        if (t < 64) Ss[t] = state[b * N_ + m0 + t];

        // ---------- Phase A: scores 32x64 over K=256 ----------
        unsigned long long accp[4][2] = {};
        for (int k0 = 0; k0 < D_; k0 += 32) {
            {   // As: 32 rows x 32 k = 256 float4, 2/thread (row-major)
                int r = t >> 3, q = t & 7;
                *(float4*)&As[r * 36 + q * 4] =
                    *(const float4*)&valb[(size_t)(n0 + r) * D_ + k0 + q * 4];
                int idx = 128 + t;
                r = idx >> 3; q = idx & 7;
                *(float4*)&As[r * 36 + q * 4] =
                    *(const float4*)&valb[(size_t)(n0 + r) * D_ + k0 + q * 4];
            }
#pragma unroll
            for (int p = 0; p < 4; p++) {  // Bs: 64x32, transpose to [kk][m]
                int idx = p * 128 + t;
                int r = idx >> 3, q = idx & 7;
                float4 v = *(const float4*)&valb[(size_t)(m0 + r) * D_ + k0 + q * 4];
                Bs[(q * 4 + 0) * 68 + r] = v.x;
                Bs[(q * 4 + 1) * 68 + r] = v.y;
                Bs[(q * 4 + 2) * 68 + r] = v.z;
                Bs[(q * 4 + 3) * 68 + r] = v.w;
            }
            __syncthreads();
#pragma unroll 16
            for (int kk = 0; kk < 32; kk++) {
                V4 bv; bv.f = *(float4*)&Bs[kk * 68 + tx * 4];
#pragma unroll
                for (int i = 0; i < 4; i++) {
                    unsigned long long a2 = dup2(As[(ty * 4 + i) * 36 + kk]);
                    accp[i][0] = ffma2(a2, bv.u[0], accp[i][0]);
                    accp[i][1] = ffma2(a2, bv.u[1], accp[i][1]);
                }
            }
            __syncthreads();
        }

        // ---------- softsign -> Es ----------
#pragma unroll
        for (int i = 0; i < 4; i++) {
            float2 lo = unpk(accp[i][0]);
            float2 hi = unpk(accp[i][1]);
            float4 e;
            e.x = lo.x / (1.f + fabsf(lo.x));
            e.y = lo.y / (1.f + fabsf(lo.y));
            e.z = hi.x / (1.f + fabsf(hi.x));
            e.w = hi.y / (1.f + fabsf(hi.y));
            *(float4*)&Es[(ty * 4 + i) * 68 + tx * 4] = e;
        }
        __syncthreads();

        // ---------- delta_state ----------
        if (t < 32) {
            float s = 0.f;
#pragma unroll
            for (int m = 0; m < 64; m++) s += Es[t * 68 + m] * Ss[m];
            ds += s;
        }

        // ---------- Phase B: dval += Es @ Pm ----------
        for (int ms = 0; ms < 64; ms += 16) {
#pragma unroll
            for (int p = 0; p < 8; p++) {  // Ps: 16x256 = 1024 float4, 8/thread
                int idx = p * 128 + t;
                int mr = idx >> 6, c = idx & 63;
                *(float4*)&Ps[mr * 256 + c * 4] =
                    *(const float4*)&pvb[(size_t)(m0 + ms + mr) * D_ + c * 4];
            }
            __syncthreads();
#pragma unroll 8
            for (int mm = 0; mm < 16; mm++) {
                unsigned long long e2[4];
#pragma unroll
                for (int i = 0; i < 4; i++)
                    e2[i] = dup2(Es[(ty * 4 + i) * 68 + ms + mm]);
#pragma unroll
                for (int q = 0; q < 4; q++) {
                    V4 pv; pv.f = *(float4*)&Ps[mm * 256 + q * 64 + tx * 4];
#pragma unroll
                    for (int i = 0; i < 4; i++) {
                        dval[i][q][0] = ffma2(e2[i], pv.u[0], dval[i][q][0]);
                        dval[i][q][1] = ffma2(e2[i], pv.u[1], dval[i][q][1]);
                    }
                }
            }
            __syncthreads();
        }
    }

    // ---------- epilogue ----------
    if (t < 32) out[b * N_ + n0 + t] = ds;
    float* dv = out + B_ * N_;
#pragma unroll
    for (int i = 0; i < 4; i++) {
#pragma unroll
        for (int q = 0; q < 4; q++) {
            V4 o; o.u[0] = dval[i][q][0]; o.u[1] = dval[i][q][1];
            *(float4*)&dv[((size_t)b * N_ + n0 + ty * 4 + i) * D_ + q * 64 + tx * 4] = o.f;
        }
    }
}

extern "C" void kernel_launch(void* const* d_in, const int* in_sizes, int n_in,
                              void* d_out, int out_size) {
    const float* val   = (const float*)d_in[0];  // [B, N, D]
    const float* state = (const float*)d_in[1];  // [B, N]
    const float* Wv    = (const float*)d_in[2];  // [D, D]
    float* out = (float*)d_out;                  // [B*N] delta_state, then [B*N*D] delta_val

    (void)in_sizes; (void)n_in; (void)out_size;

    // projval = val @ Wv
    dim3 g1(D_ / 64, (B_ * N_) / 64);
    proj_kernel<<<g1, 256>>>(val, Wv);

    // fused propagation
    dim3 g2(N_ / 32, B_);
    prop_kernel<<<g2, 128>>>(val, state, out);
}

// round 8
// speedup vs baseline: 3.0650x; 3.0650x over previous
#include <cuda_runtime.h>
#include <cuda_bf16.h>

#define B_ 4
#define N_ 4096
#define D_ 256
#define MC 32                 // m-chunk
#define NITER (N_ / MC)       // 128

// Device-global scratch (allocation-free rule)
static __device__ float          g_projval[B_ * N_ * D_];  // [b][m][e] fp32
static __device__ __nv_bfloat16  g_vhi[B_ * N_ * D_];      // [b][n][d]
static __device__ __nv_bfloat16  g_vlo[B_ * N_ * D_];
static __device__ __nv_bfloat16  g_pthi[B_ * D_ * N_];     // [b][e][m]  (P transposed)
static __device__ __nv_bfloat16  g_ptlo[B_ * D_ * N_];

// ---------------- PTX helpers (baseline ISA only: sm_80-level) ----------------
__device__ __forceinline__ unsigned smem_u32(const void* p) {
    unsigned a;
    asm("{ .reg .u64 t; cvta.to.shared.u64 t, %1; cvt.u32.u64 %0, t; }" : "=r"(a) : "l"(p));
    return a;
}
__device__ __forceinline__ void cpa16(unsigned dst, const void* src) {
    asm volatile("cp.async.cg.shared.global [%0], [%1], 16;" :: "r"(dst), "l"(src) : "memory");
}
#define CP_COMMIT() asm volatile("cp.async.commit_group;" ::: "memory")
#define CP_WAIT1()  asm volatile("cp.async.wait_group 1;" ::: "memory")

__device__ __forceinline__ void ldm4(unsigned* r, unsigned addr) {
    asm volatile("ldmatrix.sync.aligned.m8n8.x4.shared.b16 {%0,%1,%2,%3}, [%4];"
                 : "=r"(r[0]), "=r"(r[1]), "=r"(r[2]), "=r"(r[3]) : "r"(addr));
}
__device__ __forceinline__ void mmab(float* d, const unsigned* a, unsigned b0, unsigned b1) {
    asm volatile(
        "mma.sync.aligned.m16n8k16.row.col.f32.bf16.bf16.f32 "
        "{%0,%1,%2,%3}, {%4,%5,%6,%7}, {%8,%9}, {%0,%1,%2,%3};"
        : "+f"(d[0]), "+f"(d[1]), "+f"(d[2]), "+f"(d[3])
        : "r"(a[0]), "r"(a[1]), "r"(a[2]), "r"(a[3]), "r"(b0), "r"(b1));
}
__device__ __forceinline__ void sts32(unsigned addr, unsigned v) {
    asm volatile("st.shared.u32 [%0], %1;" :: "r"(addr), "r"(v) : "memory");
}

// ---------------- prologue: fp32 proj (FFMA2) + splits ----------------
__device__ __forceinline__ unsigned long long ffma2(unsigned long long a,
                                                    unsigned long long b,
                                                    unsigned long long c) {
    unsigned long long d;
    asm("fma.rn.f32x2 %0, %1, %2, %3;" : "=l"(d) : "l"(a), "l"(b), "l"(c));
    return d;
}
__device__ __forceinline__ unsigned long long dup2(float x) {
    unsigned long long d;
    asm("mov.b64 %0, {%1, %1};" : "=l"(d) : "f"(x));
    return d;
}
union V4 { float4 f; unsigned long long u[2]; };

__global__ __launch_bounds__(256, 2)
void proj_kernel(const float* __restrict__ val, const float* __restrict__ Wv) {
    __shared__ float As[64 * 36];
    __shared__ float Bs[32 * 68];
    const int t = threadIdx.x;
    const int tx = t & 15, ty = t >> 4;
    const int row0 = blockIdx.y * 64;
    const int e0 = blockIdx.x * 64;
    unsigned long long acc[4][2] = {};
    for (int k0 = 0; k0 < D_; k0 += 32) {
#pragma unroll
        for (int p = 0; p < 2; p++) {
            int idx = p * 256 + t, r = idx >> 3, q = idx & 7;
            *(float4*)&As[r * 36 + q * 4] =
                *(const float4*)&val[(size_t)(row0 + r) * D_ + k0 + q * 4];
        }
#pragma unroll
        for (int p = 0; p < 2; p++) {
            int idx = p * 256 + t, kr = idx >> 4, ec = idx & 15;
            *(float4*)&Bs[kr * 68 + ec * 4] =
                *(const float4*)&Wv[(k0 + kr) * D_ + e0 + ec * 4];
        }
        __syncthreads();
#pragma unroll 16
        for (int kk = 0; kk < 32; kk++) {
            V4 bv; bv.f = *(float4*)&Bs[kk * 68 + tx * 4];
#pragma unroll
            for (int i = 0; i < 4; i++) {
                unsigned long long a2 = dup2(As[(ty * 4 + i) * 36 + kk]);
                acc[i][0] = ffma2(a2, bv.u[0], acc[i][0]);
                acc[i][1] = ffma2(a2, bv.u[1], acc[i][1]);
            }
        }
        __syncthreads();
    }
#pragma unroll
    for (int i = 0; i < 4; i++) {
        V4 o; o.u[0] = acc[i][0]; o.u[1] = acc[i][1];
        *(float4*)&g_projval[(size_t)(row0 + ty * 4 + i) * D_ + e0 + tx * 4] = o.f;
    }
}

__global__ __launch_bounds__(256)
void split_val(const float* __restrict__ val) {
    size_t i = ((size_t)blockIdx.x * 256 + threadIdx.x) * 4;
    float4 v = *(const float4*)(val + i);
    float a[4] = {v.x, v.y, v.z, v.w};
#pragma unroll
    for (int k = 0; k < 4; k += 2) {
        __nv_bfloat16 h0 = __float2bfloat16(a[k]);
        __nv_bfloat16 h1 = __float2bfloat16(a[k + 1]);
        __nv_bfloat162 hp; hp.x = h0; hp.y = h1;
        __nv_bfloat162 lp;
        lp.x = __float2bfloat16(a[k] - __bfloat162float(h0));
        lp.y = __float2bfloat16(a[k + 1] - __bfloat162float(h1));
        *(__nv_bfloat162*)(g_vhi + i + k) = hp;
        *(__nv_bfloat162*)(g_vlo + i + k) = lp;
    }
}

__global__ __launch_bounds__(256)
void trans_split() {
    __shared__ float ts[32][33];
    const int b = blockIdx.z, e0 = blockIdx.y * 32, m0 = blockIdx.x * 32;
    const int tx = threadIdx.x, ty = threadIdx.y;  // (32, 8)
    const float* src = g_projval + ((size_t)(b * N_ + m0)) * D_ + e0;
#pragma unroll
    for (int i = 0; i < 4; i++)
        ts[ty + 8 * i][tx] = src[(size_t)(ty + 8 * i) * D_ + tx];
    __syncthreads();
#pragma unroll
    for (int i = 0; i < 4; i++) {
        int e = ty + 8 * i;
        float v = ts[tx][e];
        __nv_bfloat16 h = __float2bfloat16(v);
        __nv_bfloat16 l = __float2bfloat16(v - __bfloat162float(h));
        size_t o = (size_t)(b * D_ + e0 + e) * N_ + m0 + tx;
        g_pthi[o] = h;
        g_ptlo[o] = l;
    }
}

// ---------------- main fused kernel (warp-level mma.sync / HMMA) ----------------
// SMEM layout (bytes)
#define OFF_VNH 0u         // Vn_hi 128 rows x 512B (swizzled)      65536
#define OFF_VNL 65536u     // Vn_lo                                  65536
#define OFF_VMH 131072u    // Vm_hi 32 x 512B                        16384
#define OFF_VML 147456u
#define OFF_PTH 163840u    // Pt_hi 256 rows x 80B (64B data + pad)  20480
#define OFF_PTL 184320u
#define OFF_EH  204800u    // E_hi 128 rows x 80B                    10240
#define OFF_EL  215040u
#define OFF_DS  225280u    // 128 floats
#define SMEM_SZ 225792u

__global__ __launch_bounds__(512, 1)
void prop_mma(const float* __restrict__ state, float* __restrict__ out) {
    extern __shared__ __align__(128) char sm[];
    const unsigned sb = smem_u32(sm);
    const int t = threadIdx.x;
    const int lane = t & 31, w = t >> 5;
    const int rg = w >> 1, ch = w & 1;
    const int RG = rg * 16;
    const int b = blockIdx.y;
    const int n0 = blockIdx.x * 128;

    const __nv_bfloat16* vh  = g_vhi  + (size_t)b * N_ * D_;
    const __nv_bfloat16* vl  = g_vlo  + (size_t)b * N_ * D_;
    const __nv_bfloat16* pth = g_pthi + (size_t)b * D_ * N_;
    const __nv_bfloat16* ptl = g_ptlo + (size_t)b * D_ * N_;
    const float* stb = state + b * N_;

    float* ds_sm = (float*)(sm + OFF_DS);
    if (t < 128) ds_sm[t] = 0.f;

    // ---- Vn (persistent) + Vm(0) : commit group 0 ----
#pragma unroll
    for (int j = 0; j < 8; j++) {
        int idx = j * 512 + t, row = idx >> 5, kc = idx & 31;
        unsigned swz = (unsigned)(row * 512) + (((unsigned)kc * 16) ^ (((unsigned)row & 7) << 4));
        cpa16(sb + OFF_VNH + swz, vh + (size_t)(n0 + row) * D_ + kc * 8);
        cpa16(sb + OFF_VNL + swz, vl + (size_t)(n0 + row) * D_ + kc * 8);
    }
#pragma unroll
    for (int j = 0; j < 2; j++) {
        int idx = j * 512 + t, row = idx >> 5, kc = idx & 31;
        unsigned swz = (unsigned)(row * 512) + (((unsigned)kc * 16) ^ (((unsigned)row & 7) << 4));
        cpa16(sb + OFF_VMH + swz, vh + (size_t)row * D_ + kc * 8);
        cpa16(sb + OFF_VML + swz, vl + (size_t)row * D_ + kc * 8);
    }
    CP_COMMIT();
    // ---- Pt(0) : commit group 1 ----
#pragma unroll
    for (int j = 0; j < 2; j++) {
        int idx = j * 512 + t, row = idx >> 2, kc = idx & 3;
        unsigned o = (unsigned)(row * 80 + kc * 16);
        cpa16(sb + OFF_PTH + o, pth + (size_t)row * N_ + kc * 8);
        cpa16(sb + OFF_PTL + o, ptl + (size_t)row * N_ + kc * 8);
    }
    CP_COMMIT();

    float accD[64];
#pragma unroll
    for (int q = 0; q < 64; q++) accD[q] = 0.f;
    float ds0 = 0.f, ds1 = 0.f;

    // fragment address components
    const unsigned aRow = RG + (lane & 15);
    const unsigned aK   = ((unsigned)lane >> 4) * 16;        // byte offset within k16
    const unsigned aSw  = (aRow & 7) << 4;
    const unsigned aBase = aRow * 512;
    const unsigned bRow = (unsigned)(ch * 16) + (((unsigned)lane >> 4) << 3) + (lane & 7);
    const unsigned bK   = (((unsigned)lane >> 3) & 1) * 16;
    const unsigned bSw  = (bRow & 7) << 4;
    const unsigned bBase = bRow * 512;
    const unsigned eOff = (RG + (lane & 15)) * 80 + ((unsigned)lane >> 4) * 16;
    const unsigned pOff = ((unsigned)(ch * 128) + (((unsigned)lane >> 4) << 3) + (lane & 7)) * 80
                        + (((unsigned)lane >> 3) & 1) * 16;
    const int r = lane >> 2, c = (lane & 3) * 2;

#pragma unroll 1
    for (int i = 0; i < NITER; i++) {
        const int m0 = i * MC;
        CP_WAIT1();            // Vm(i) ready (and Vn on i==0)
        __syncthreads();

        // -------- Phase A: S[128x32] = Vn . Vm^T, split-bf16 (hh+hl+lh) --------
        float accS[8];
#pragma unroll
        for (int q = 0; q < 8; q++) accS[q] = 0.f;
#pragma unroll
        for (int ks = 0; ks < 16; ks++) {
            unsigned ah[4], al[4], bh[4], bl[4];
            unsigned ka = ((unsigned)(ks * 32) + aK) ^ aSw;
            ldm4(ah, sb + OFF_VNH + aBase + ka);
            ldm4(al, sb + OFF_VNL + aBase + ka);
            unsigned kb = ((unsigned)(ks * 32) + bK) ^ bSw;
            ldm4(bh, sb + OFF_VMH + bBase + kb);
            ldm4(bl, sb + OFF_VML + bBase + kb);
            mmab(accS,     ah, bh[0], bh[1]);
            mmab(accS,     ah, bl[0], bl[1]);
            mmab(accS,     al, bh[0], bh[1]);
            mmab(accS + 4, ah, bh[2], bh[3]);
            mmab(accS + 4, ah, bl[2], bl[3]);
            mmab(accS + 4, al, bh[2], bh[3]);
        }
        __syncthreads();       // all Vm reads done

        // prefetch Vm(i+1) (clamped on last iter to keep group counts uniform)
        const int m1 = (i < NITER - 1) ? m0 + MC : 0;
#pragma unroll
        for (int j = 0; j < 2; j++) {
            int idx = j * 512 + t, row = idx >> 5, kc = idx & 31;
            unsigned swz = (unsigned)(row * 512) + (((unsigned)kc * 16) ^ (((unsigned)row & 7) << 4));
            cpa16(sb + OFF_VMH + swz, vh + (size_t)(m1 + row) * D_ + kc * 8);
            cpa16(sb + OFF_VML + swz, vl + (size_t)(m1 + row) * D_ + kc * 8);
        }
        CP_COMMIT();

        // -------- epilogue: softsign, delta_state, E hi/lo -> SMEM --------
#pragma unroll
        for (int tl = 0; tl < 2; tl++) {
            int Cb = ch * 16 + tl * 8 + c;
            float sc0 = __ldg(stb + m0 + Cb);
            float sc1 = __ldg(stb + m0 + Cb + 1);
            float s0 = accS[tl * 4 + 0], s1 = accS[tl * 4 + 1];
            float s2 = accS[tl * 4 + 2], s3 = accS[tl * 4 + 3];
            float e0 = __fdividef(s0, 1.f + fabsf(s0));
            float e1 = __fdividef(s1, 1.f + fabsf(s1));
            float e2 = __fdividef(s2, 1.f + fabsf(s2));
            float e3 = __fdividef(s3, 1.f + fabsf(s3));
            ds0 += e0 * sc0 + e1 * sc1;
            ds1 += e2 * sc0 + e3 * sc1;
            __nv_bfloat16 h0 = __float2bfloat16(e0), h1 = __float2bfloat16(e1);
            __nv_bfloat16 h2 = __float2bfloat16(e2), h3 = __float2bfloat16(e3);
            __nv_bfloat162 hp01; hp01.x = h0; hp01.y = h1;
            __nv_bfloat162 hp23; hp23.x = h2; hp23.y = h3;
            __nv_bfloat162 lp01, lp23;
            lp01.x = __float2bfloat16(e0 - __bfloat162float(h0));
            lp01.y = __float2bfloat16(e1 - __bfloat162float(h1));
            lp23.x = __float2bfloat16(e2 - __bfloat162float(h2));
            lp23.y = __float2bfloat16(e3 - __bfloat162float(h3));
            unsigned o0 = (unsigned)((RG + r) * 80 + Cb * 2);
            unsigned o1 = o0 + 8 * 80;
            sts32(sb + OFF_EH + o0, *(unsigned*)&hp01);
            sts32(sb + OFF_EL + o0, *(unsigned*)&lp01);
            sts32(sb + OFF_EH + o1, *(unsigned*)&hp23);
            sts32(sb + OFF_EL + o1, *(unsigned*)&lp23);
        }
        CP_WAIT1();            // Pt(i) ready
        __syncthreads();       // E + Pt visible

        // -------- Phase B: dval[128x256] += E . Pt^T, split-bf16 --------
#pragma unroll
        for (int ks = 0; ks < 2; ks++) {
            unsigned eh[4], el[4];
            ldm4(eh, sb + OFF_EH + eOff + ks * 32);
            ldm4(el, sb + OFF_EL + eOff + ks * 32);
#pragma unroll
            for (int g = 0; g < 8; g++) {
                unsigned ph[4], pl[4];
                unsigned po = pOff + (unsigned)(g * 16 * 80 + ks * 32);
                ldm4(ph, sb + OFF_PTH + po);
                ldm4(pl, sb + OFF_PTL + po);
                float* d0 = accD + (g * 2 + 0) * 4;
                float* d1 = accD + (g * 2 + 1) * 4;
                mmab(d0, eh, ph[0], ph[1]);
                mmab(d0, eh, pl[0], pl[1]);
                mmab(d0, el, ph[0], ph[1]);
                mmab(d1, eh, ph[2], ph[3]);
                mmab(d1, eh, pl[2], pl[3]);
                mmab(d1, el, ph[2], ph[3]);
            }
        }
        __syncthreads();       // all Pt reads done

        // prefetch Pt(i+1) (clamped)
#pragma unroll
        for (int j = 0; j < 2; j++) {
            int idx = j * 512 + t, row = idx >> 2, kc = idx & 3;
            unsigned o = (unsigned)(row * 80 + kc * 16);
            cpa16(sb + OFF_PTH + o, pth + (size_t)row * N_ + m1 + kc * 8);
            cpa16(sb + OFF_PTL + o, ptl + (size_t)row * N_ + m1 + kc * 8);
        }
        CP_COMMIT();
    }

    // -------- write delta_val --------
    float* dvb = out + B_ * N_ + ((size_t)(b * N_ + n0)) * D_;
#pragma unroll
    for (int g = 0; g < 8; g++) {
#pragma unroll
        for (int h2 = 0; h2 < 2; h2++) {
            int col = ch * 128 + g * 16 + h2 * 8 + c;
            const float* d = accD + (g * 2 + h2) * 4;
            float2 lo; lo.x = d[0]; lo.y = d[1];
            float2 hi; hi.x = d[2]; hi.y = d[3];
            *(float2*)(dvb + (size_t)(RG + r) * D_ + col) = lo;
            *(float2*)(dvb + (size_t)(RG + r + 8) * D_ + col) = hi;
        }
    }

    // -------- reduce & write delta_state --------
    ds0 += __shfl_xor_sync(0xffffffffu, ds0, 1);
    ds0 += __shfl_xor_sync(0xffffffffu, ds0, 2);
    ds1 += __shfl_xor_sync(0xffffffffu, ds1, 1);
    ds1 += __shfl_xor_sync(0xffffffffu, ds1, 2);
    if ((lane & 3) == 0) {
        atomicAdd(ds_sm + RG + r, ds0);
        atomicAdd(ds_sm + RG + r + 8, ds1);
    }
    __syncthreads();
    if (t < 128) out[b * N_ + n0 + t] = ds_sm[t];
}

extern "C" void kernel_launch(void* const* d_in, const int* in_sizes, int n_in,
                              void* d_out, int out_size) {
    const float* val   = (const float*)d_in[0];  // [B, N, D]
    const float* state = (const float*)d_in[1];  // [B, N]
    const float* Wv    = (const float*)d_in[2];  // [D, D]
    float* out = (float*)d_out;                  // [B*N] delta_state, [B*N*D] delta_val
    (void)in_sizes; (void)n_in; (void)out_size;

    cudaFuncSetAttribute(prop_mma, cudaFuncAttributeMaxDynamicSharedMemorySize, SMEM_SZ);

    split_val<<<(B_ * N_ * D_) / 1024, 256>>>(val);
    proj_kernel<<<dim3(D_ / 64, (B_ * N_) / 64), 256>>>(val, Wv);
    trans_split<<<dim3(N_ / 32, D_ / 32, B_), dim3(32, 8)>>>();
    prop_mma<<<dim3(N_ / 128, B_), 512, SMEM_SZ>>>(state, out);
}